// round 1
// baseline (speedup 1.0000x reference)
#include <cuda_runtime.h>

#define TT   8192
#define NTH  256
#define CH   32              // TT / NTH
#define FEPS 1e-8f
#define SC_SZ 8448           // 8192 + 8192/32 skew padding
#define SMEM_BYTES ((2*SC_SZ + 4*NTH) * 4)

__device__ __forceinline__ int PADI(int i) { return i + (i >> 5); }

#define GX(j) (sc[PADI(((j) < 0) ? 0 : (j))])

extern "C" __global__ void __launch_bounds__(NTH)
feat_kernel(const float* __restrict__ gclose, float* __restrict__ gout, size_t BT)
{
    extern __shared__ float sm[];
    float* sc  = sm;                 // padded close
    float* sa  = sm + SC_SZ;         // padded aux: macd, then sq_diff
    float* sb0 = sm + 2 * SC_SZ;     // scan buffers (4 x 256)
    float* sb1 = sb0 + NTH;
    float* sb2 = sb1 + NTH;
    float* sb3 = sb2 + NTH;

    const int row = blockIdx.x;
    const int tid = threadIdx.x;
    const int t0  = tid * CH;
    const float* x = gclose + (size_t)row * TT;
    float* obase = gout + (size_t)row * TT + t0;

    // ---- load close row into skewed shared (coalesced float4 reads) ----
    {
        const float4* x4 = (const float4*)x;
        #pragma unroll
        for (int i = 0; i < TT / (4 * NTH); ++i) {
            int i4 = tid + i * NTH;
            float4 v = x4[i4];
            int b = i4 * 4;
            sc[PADI(b)]     = v.x;
            sc[PADI(b + 1)] = v.y;
            sc[PADI(b + 2)] = v.z;
            sc[PADI(b + 3)] = v.w;
        }
    }
    __syncthreads();
    const float x0 = sc[0];

    // ================= EMA12 / EMA26 -> MACD (feature 9) =================
    const float aF = 2.0f / 13.0f, omF = 1.0f - aF;
    const float aS = 2.0f / 27.0f, omS = 1.0f - aS;
    {
        float cF = 1.f, dF = 0.f, cS = 1.f, dS = 0.f;
        if (tid == 0) {
            float yF = x0, yS = x0;
            #pragma unroll 1
            for (int j = 1; j < CH; ++j) {
                float v = sc[PADI(j)];
                yF = fmaf(aF, v, omF * yF);
                yS = fmaf(aS, v, omS * yS);
            }
            cF = 0.f; dF = yF; cS = 0.f; dS = yS;
        } else {
            #pragma unroll 1
            for (int j = 0; j < CH; ++j) {
                float v = sc[PADI(t0 + j)];
                dF = fmaf(aF, v, omF * dF); cF *= omF;
                dS = fmaf(aS, v, omS * dS); cS *= omS;
            }
        }
        sb0[tid] = cF; sb1[tid] = dF; sb2[tid] = cS; sb3[tid] = dS;
        __syncthreads();
        #pragma unroll 1
        for (int off = 1; off < NTH; off <<= 1) {
            float ccF = sb0[tid], cdF = sb1[tid], ccS = sb2[tid], cdS = sb3[tid];
            float pcF = 0.f, pdF = 0.f, pcS = 0.f, pdS = 0.f;
            if (tid >= off) { pcF = sb0[tid-off]; pdF = sb1[tid-off];
                              pcS = sb2[tid-off]; pdS = sb3[tid-off]; }
            __syncthreads();
            if (tid >= off) {
                sb0[tid] = pcF * ccF; sb1[tid] = fmaf(pdF, ccF, cdF);
                sb2[tid] = pcS * ccS; sb3[tid] = fmaf(pdS, ccS, cdS);
            }
            __syncthreads();
        }
        float yF = (tid > 0) ? sb1[tid - 1] : x0;
        float yS = (tid > 0) ? sb3[tid - 1] : x0;
        __syncthreads();

        float* om = obase + 9 * BT;
        #pragma unroll 1
        for (int g = 0; g < CH / 4; ++g) {
            float mb[4];
            #pragma unroll
            for (int jj = 0; jj < 4; ++jj) {
                int t = t0 + g * 4 + jj;
                float v = sc[PADI(t)];
                if (t > 0) {
                    yF = fmaf(aF, v, omF * yF);
                    yS = fmaf(aS, v, omS * yS);
                }
                float m = yF - yS;
                sa[PADI(t)] = m;
                mb[jj] = m;
            }
            *(float4*)(om + g * 4) = make_float4(mb[0], mb[1], mb[2], mb[3]);
        }
    }
    // (each thread only reads its own chunk of sa below for local scan -> no sync needed;
    //  scan buffers were already synced above)

    // ================= EMA9 over MACD -> signal (10), hist (11) ==========
    const float aG = 0.2f, omG = 0.8f;
    {
        float cG = 1.f, dG = 0.f;
        if (tid == 0) {
            float y = sa[0];
            #pragma unroll 1
            for (int j = 1; j < CH; ++j) y = fmaf(aG, sa[PADI(j)], omG * y);
            cG = 0.f; dG = y;
        } else {
            #pragma unroll 1
            for (int j = 0; j < CH; ++j) { dG = fmaf(aG, sa[PADI(t0 + j)], omG * dG); cG *= omG; }
        }
        sb0[tid] = cG; sb1[tid] = dG;
        __syncthreads();
        #pragma unroll 1
        for (int off = 1; off < NTH; off <<= 1) {
            float cc = sb0[tid], cd = sb1[tid], pc = 0.f, pd = 0.f;
            if (tid >= off) { pc = sb0[tid-off]; pd = sb1[tid-off]; }
            __syncthreads();
            if (tid >= off) { sb0[tid] = pc * cc; sb1[tid] = fmaf(pd, cc, cd); }
            __syncthreads();
        }
        float y = (tid > 0) ? sb1[tid - 1] : sa[0];
        __syncthreads();

        float* osig = obase + 10 * BT;
        float* ohst = obase + 11 * BT;
        #pragma unroll 1
        for (int g = 0; g < CH / 4; ++g) {
            float sbf[4], hbf[4];
            #pragma unroll
            for (int jj = 0; jj < 4; ++jj) {
                int t = t0 + g * 4 + jj;
                float m = sa[PADI(t)];
                if (t > 0) y = fmaf(aG, m, omG * y);
                sbf[jj] = y; hbf[jj] = m - y;
            }
            *(float4*)(osig + g * 4) = make_float4(sbf[0], sbf[1], sbf[2], sbf[3]);
            *(float4*)(ohst + g * 4) = make_float4(hbf[0], hbf[1], hbf[2], hbf[3]);
        }
    }
    __syncthreads();   // sa will be overwritten with sq_diff

    // ====== Sliding windows: MA5/10/20/50 + ratios (0..7), RSI (8), ATR (16)
    {
        float s5 = 0.f, s10 = 0.f, s20 = 0.f, s50 = 0.f, gs = 0.f, ls = 0.f;
        #pragma unroll 1
        for (int k = 1; k <= 50; ++k) {
            float v = GX(t0 - k);
            s50 += v;
            if (k <= 20) s20 += v;
            if (k <= 10) s10 += v;
            if (k <= 5)  s5  += v;
        }
        #pragma unroll 1
        for (int k = 1; k <= 14; ++k) {
            int j = t0 - k;
            if (j >= 1) {
                float d = sc[PADI(j)] - sc[PADI(j - 1)];
                gs += fmaxf(d, 0.f);
                ls += fmaxf(-d, 0.f);
            }
        }
        float xprev = GX(t0 - 1);
        #pragma unroll 1
        for (int g = 0; g < CH / 4; ++g) {
            float a0[4], a1[4], a2[4], a3[4], a4[4], a5v[4], a6[4], a7[4], a8[4], a9[4];
            #pragma unroll
            for (int jj = 0; jj < 4; ++jj) {
                int t = t0 + g * 4 + jj;
                float xt = sc[PADI(t)];
                s5  += xt - GX(t - 5);
                s10 += xt - GX(t - 10);
                s20 += xt - GX(t - 20);
                s50 += xt - GX(t - 50);
                float d = (t >= 1) ? (xt - xprev) : 0.f;
                gs += fmaxf(d, 0.f);
                ls += fmaxf(-d, 0.f);
                int jl = t - 14;
                if (jl >= 1) {
                    float dl = sc[PADI(jl)] - sc[PADI(jl - 1)];
                    gs -= fmaxf(dl, 0.f);
                    ls -= fmaxf(-dl, 0.f);
                }
                float ma5  = s5  * 0.2f;
                float ma10 = s10 * 0.1f;
                float ma20 = s20 * 0.05f;
                float ma50 = s50 * 0.02f;
                a0[jj] = ma5;  a1[jj] = __fdividef(xt, ma5  + FEPS);
                a2[jj] = ma10; a3[jj] = __fdividef(xt, ma10 + FEPS);
                a4[jj] = ma20; a5v[jj] = __fdividef(xt, ma20 + FEPS);
                a6[jj] = ma50; a7[jj] = __fdividef(xt, ma50 + FEPS);
                float ag = gs * (1.f / 14.f), al = ls * (1.f / 14.f);
                float rs = __fdividef(ag, al + FEPS);
                a8[jj] = 100.f - __fdividef(100.f, 1.f + rs);
                a9[jj] = ag + al;                       // ATR = MA14(gain)+MA14(loss)
                float df = xt - ma20;
                sa[PADI(t)] = df * df;                  // sq_diff for Bollinger
                xprev = xt;
            }
            int go = g * 4;
            *(float4*)(obase + 0 * BT + go)  = make_float4(a0[0], a0[1], a0[2], a0[3]);
            *(float4*)(obase + 1 * BT + go)  = make_float4(a1[0], a1[1], a1[2], a1[3]);
            *(float4*)(obase + 2 * BT + go)  = make_float4(a2[0], a2[1], a2[2], a2[3]);
            *(float4*)(obase + 3 * BT + go)  = make_float4(a3[0], a3[1], a3[2], a3[3]);
            *(float4*)(obase + 4 * BT + go)  = make_float4(a4[0], a4[1], a4[2], a4[3]);
            *(float4*)(obase + 5 * BT + go)  = make_float4(a5v[0], a5v[1], a5v[2], a5v[3]);
            *(float4*)(obase + 6 * BT + go)  = make_float4(a6[0], a6[1], a6[2], a6[3]);
            *(float4*)(obase + 7 * BT + go)  = make_float4(a7[0], a7[1], a7[2], a7[3]);
            *(float4*)(obase + 8 * BT + go)  = make_float4(a8[0], a8[1], a8[2], a8[3]);
            *(float4*)(obase + 16 * BT + go) = make_float4(a9[0], a9[1], a9[2], a9[3]);
        }
    }
    __syncthreads();   // sq_diff from all threads visible

    // ====== Bollinger (12,13,14) + %B (15) ======
    {
        const float sqpad = sa[0];    // sq_diff[0] (padding value)
        float sbm = 0.f, sv = 0.f;
        #pragma unroll 1
        for (int k = 1; k <= 20; ++k) {
            int j = t0 - k;
            sbm += GX(j);
            sv  += (j < 0) ? sqpad : sa[PADI(j)];
        }
        #pragma unroll 1
        for (int g = 0; g < CH / 4; ++g) {
            float b0[4], b1[4], b2[4], b3[4];
            #pragma unroll
            for (int jj = 0; jj < 4; ++jj) {
                int t = t0 + g * 4 + jj;
                float xt = sc[PADI(t)];
                sbm += xt - GX(t - 20);
                int j2 = t - 20;
                float sqold = (j2 < 0) ? sqpad : sa[PADI(j2)];
                sv += sa[PADI(t)] - sqold;
                float ma  = sbm * 0.05f;
                float var = fmaxf(sv, 0.f) * 0.05f;
                float sd  = sqrtf(var + FEPS);
                float bbu = ma + 2.f * sd;
                float bbl = ma - 2.f * sd;
                b0[jj] = bbu; b1[jj] = ma; b2[jj] = bbl;
                b3[jj] = __fdividef(xt - bbl, bbu - bbl + FEPS);
            }
            int go = g * 4;
            *(float4*)(obase + 12 * BT + go) = make_float4(b0[0], b0[1], b0[2], b0[3]);
            *(float4*)(obase + 13 * BT + go) = make_float4(b1[0], b1[1], b1[2], b1[3]);
            *(float4*)(obase + 14 * BT + go) = make_float4(b2[0], b2[1], b2[2], b2[3]);
            *(float4*)(obase + 15 * BT + go) = make_float4(b3[0], b3[1], b3[2], b3[3]);
        }
    }
}

extern "C" void kernel_launch(void* const* d_in, const int* in_sizes, int n_in,
                              void* d_out, int out_size)
{
    const float* close = (const float*)d_in[0];
    float* out = (float*)d_out;
    int B = in_sizes[0] / TT;                 // 512
    size_t BT = (size_t)B * TT;
    cudaFuncSetAttribute(feat_kernel, cudaFuncAttributeMaxDynamicSharedMemorySize, SMEM_BYTES);
    feat_kernel<<<B, NTH, SMEM_BYTES>>>(close, out, BT);
}

// round 2
// speedup vs baseline: 1.0166x; 1.0166x over previous
#include <cuda_runtime.h>

#define TT   8192
#define NTH  256
#define CH   32
#define NW   (NTH/32)
#define FEPS 1e-8f
#define SC_SZ (TT + TT/32)    // 8448

__device__ __forceinline__ int PADI(int i) { return i + (i >> 5); }
#define GX(j) (sc[PADI(((j) < 0) ? 0 : (j))])

// generic affine inclusive warp scan: state (c,d) == y_out = c*y_in + d
__device__ __forceinline__ void wscan(float& c, float& d, int lane) {
    #pragma unroll
    for (int off = 1; off < 32; off <<= 1) {
        float pc = __shfl_up_sync(0xffffffffu, c, off);
        float pd = __shfl_up_sync(0xffffffffu, d, off);
        if (lane >= off) { d = fmaf(pd, c, d); c *= pc; }
    }
}

extern "C" __global__ void __launch_bounds__(NTH, 4)
feat_kernel(const float* __restrict__ gclose, float* __restrict__ gout, size_t BT)
{
    __shared__ float sc[SC_SZ];
    __shared__ float swA[NW], swB[NW], swC[NW];

    const int row  = blockIdx.x;
    const int tid  = threadIdx.x;
    const int lane = tid & 31;
    const int wid  = tid >> 5;
    const int t0   = tid * CH;
    const float* x = gclose + (size_t)row * TT;
    float* obase   = gout + (size_t)row * TT + t0;
    const float* so = sc + t0 + tid;   // own chunk: sc[PADI(t0+k)] == so[k]

    // ---- load row into skewed shared ----
    {
        const float4* x4 = (const float4*)x;
        #pragma unroll
        for (int i = 0; i < TT / (4 * NTH); ++i) {
            int i4 = tid + i * NTH;
            float4 v = x4[i4];
            int b = i4 * 4;
            sc[PADI(b)]     = v.x;
            sc[PADI(b + 1)] = v.y;
            sc[PADI(b + 2)] = v.z;
            sc[PADI(b + 3)] = v.w;
        }
    }
    __syncthreads();
    const float x0 = sc[0];

    const float aF = 2.0f / 13.0f, omF = 1.0f - aF;
    const float aS = 2.0f / 27.0f, omS = 1.0f - aS;
    const float aG = 0.2f,         omG = 0.8f;

    // ================= pass A: EMA12/26 local affine + warp scan =========
    float yF0, yS0;
    {
        float cF, dF, cS, dS;
        if (tid == 0) {
            float yF = x0, yS = x0;
            #pragma unroll 1
            for (int k = 1; k < CH; ++k) {
                float v = so[k];
                yF = fmaf(aF, v, omF * yF);
                yS = fmaf(aS, v, omS * yS);
            }
            cF = 0.f; dF = yF; cS = 0.f; dS = yS;
        } else {
            cF = 1.f; dF = 0.f; cS = 1.f; dS = 0.f;
            #pragma unroll 1
            for (int k = 0; k < CH; ++k) {
                float v = so[k];
                dF = fmaf(aF, v, omF * dF); cF *= omF;
                dS = fmaf(aS, v, omS * dS); cS *= omS;
            }
        }
        wscan(cF, dF, lane);
        wscan(cS, dS, lane);
        if (lane == 31) { swA[wid] = dF; swB[wid] = dS; }
        float uF  = __shfl_up_sync(0xffffffffu, dF, 1);
        float ucF = __shfl_up_sync(0xffffffffu, cF, 1);
        float uS  = __shfl_up_sync(0xffffffffu, dS, 1);
        float ucS = __shfl_up_sync(0xffffffffu, cS, 1);
        __syncthreads();
        float pF = (wid > 0) ? swA[wid - 1] : 0.f;   // om^1024 kills deeper terms (fp32-exact)
        float pS = (wid > 0) ? swB[wid - 1] : 0.f;
        if (lane == 0) { yF0 = pF; yS0 = pS; }
        else           { yF0 = fmaf(ucF, pF, uF); yS0 = fmaf(ucS, pS, uS); }
    }

    // ========== pass B: replay -> macd, EMA9 local affine + scan =========
    float y90;
    {
        float cG, dG;
        if (tid == 0) {
            float yF = x0, yS = x0, y9 = 0.f;   // macd(0) = 0
            #pragma unroll 1
            for (int k = 1; k < CH; ++k) {
                float v = so[k];
                yF = fmaf(aF, v, omF * yF);
                yS = fmaf(aS, v, omS * yS);
                float m = yF - yS;
                y9 = fmaf(aG, m, omG * y9);
            }
            cG = 0.f; dG = y9;
        } else {
            float yF = yF0, yS = yS0;
            cG = 1.f; dG = 0.f;
            #pragma unroll 1
            for (int k = 0; k < CH; ++k) {
                float v = so[k];
                yF = fmaf(aF, v, omF * yF);
                yS = fmaf(aS, v, omS * yS);
                float m = yF - yS;
                dG = fmaf(aG, m, omG * dG); cG *= omG;
            }
        }
        wscan(cG, dG, lane);
        if (lane == 31) swC[wid] = dG;
        float uG  = __shfl_up_sync(0xffffffffu, dG, 1);
        float ucG = __shfl_up_sync(0xffffffffu, cG, 1);
        __syncthreads();
        float pG = (wid > 0) ? swC[wid - 1] : 0.f;
        y90 = (lane == 0) ? pG : fmaf(ucG, pG, uG);
    }

    // ========== pass C: emit macd (9), signal (10), hist (11) ============
    {
        float yF = yF0, yS = yS0, y9 = y90;
        float* om  = obase + 9  * BT;
        float* osg = obase + 10 * BT;
        float* oh  = obase + 11 * BT;
        #pragma unroll 1
        for (int g = 0; g < CH / 4; ++g) {
            float mb[4], sb[4], hb[4];
            #pragma unroll
            for (int jj = 0; jj < 4; ++jj) {
                int k = g * 4 + jj;
                int t = t0 + k;
                float v = so[k];
                if (t > 0) {
                    yF = fmaf(aF, v, omF * yF);
                    yS = fmaf(aS, v, omS * yS);
                } else { yF = x0; yS = x0; }
                float m = yF - yS;
                if (t > 0) y9 = fmaf(aG, m, omG * y9);
                else       y9 = m;
                mb[jj] = m; sb[jj] = y9; hb[jj] = m - y9;
            }
            int go = g * 4;
            *(float4*)(om  + go) = make_float4(mb[0], mb[1], mb[2], mb[3]);
            *(float4*)(osg + go) = make_float4(sb[0], sb[1], sb[2], sb[3]);
            *(float4*)(oh  + go) = make_float4(hb[0], hb[1], hb[2], hb[3]);
        }
    }

    // ====== windows pass: MA5/10/20/50 + ratios (0..7), RSI (8), ATR (16)
    {
        float s5 = 0.f, s10 = 0.f, s20 = 0.f, s50 = 0.f, gs = 0.f, ls = 0.f;
        #pragma unroll 1
        for (int k = 1; k <= 50; ++k) {
            float v = GX(t0 - k);
            s50 += v;
            if (k <= 20) s20 += v;
            if (k <= 10) s10 += v;
            if (k <= 5)  s5  += v;
        }
        #pragma unroll 1
        for (int k = 1; k <= 14; ++k) {
            int j = t0 - k;
            if (j >= 1) {
                float d = sc[PADI(j)] - sc[PADI(j - 1)];
                gs += fmaxf(d, 0.f);
                ls += fmaxf(-d, 0.f);
            }
        }
        float xprev = GX(t0 - 1);
        float xm15  = GX(t0 - 15);
        #pragma unroll 1
        for (int g = 0; g < CH / 4; ++g) {
            float a0[4], a1[4], a2[4], a3[4], a4[4], a5v[4], a6[4], a7[4], a8[4], a9[4];
            #pragma unroll
            for (int jj = 0; jj < 4; ++jj) {
                int k = g * 4 + jj;
                int t = t0 + k;
                float xt = so[k];
                s5  += xt - GX(t - 5);
                s10 += xt - GX(t - 10);
                s20 += xt - GX(t - 20);
                s50 += xt - GX(t - 50);
                float d = (t >= 1) ? (xt - xprev) : 0.f;
                gs += fmaxf(d, 0.f);
                ls += fmaxf(-d, 0.f);
                float xm14 = GX(t - 14);
                if (t - 14 >= 1) {
                    float dl = xm14 - xm15;
                    gs -= fmaxf(dl, 0.f);
                    ls -= fmaxf(-dl, 0.f);
                }
                xm15 = xm14;
                float ma5  = s5  * 0.2f;
                float ma10 = s10 * 0.1f;
                float ma20 = s20 * 0.05f;
                float ma50 = s50 * 0.02f;
                a0[jj] = ma5;  a1[jj]  = __fdividef(xt, ma5  + FEPS);
                a2[jj] = ma10; a3[jj]  = __fdividef(xt, ma10 + FEPS);
                a4[jj] = ma20; a5v[jj] = __fdividef(xt, ma20 + FEPS);
                a6[jj] = ma50; a7[jj]  = __fdividef(xt, ma50 + FEPS);
                a8[jj] = 100.f * __fdividef(gs, gs + ls + 14.f * FEPS);
                a9[jj] = (gs + ls) * (1.f / 14.f);
                xprev = xt;
            }
            int go = g * 4;
            *(float4*)(obase + 0  * BT + go) = make_float4(a0[0], a0[1], a0[2], a0[3]);
            *(float4*)(obase + 1  * BT + go) = make_float4(a1[0], a1[1], a1[2], a1[3]);
            *(float4*)(obase + 2  * BT + go) = make_float4(a2[0], a2[1], a2[2], a2[3]);
            *(float4*)(obase + 3  * BT + go) = make_float4(a3[0], a3[1], a3[2], a3[3]);
            *(float4*)(obase + 4  * BT + go) = make_float4(a4[0], a4[1], a4[2], a4[3]);
            *(float4*)(obase + 5  * BT + go) = make_float4(a5v[0], a5v[1], a5v[2], a5v[3]);
            *(float4*)(obase + 6  * BT + go) = make_float4(a6[0], a6[1], a6[2], a6[3]);
            *(float4*)(obase + 7  * BT + go) = make_float4(a7[0], a7[1], a7[2], a7[3]);
            *(float4*)(obase + 8  * BT + go) = make_float4(a8[0], a8[1], a8[2], a8[3]);
            *(float4*)(obase + 16 * BT + go) = make_float4(a9[0], a9[1], a9[2], a9[3]);
        }
    }

    // ====== Bollinger (12,13,14) + %B (15), no aux buffer ======
    // var(t) = [Σx² − 2Σx·ma + Σma²]/20 over j=t-19..t, ma(j) = MA20(j)
    {
        float w = 0.f;
        #pragma unroll 1
        for (int k = 0; k < 20; ++k) w += GX(t0 - 40 + k);   // 20-sum ending t0-21
        float wd = w;                                         // delayed tracker
        float A = 0.f, Bs = 0.f, Cs = 0.f;
        #pragma unroll 1
        for (int j = t0 - 20; j <= t0 - 1; ++j) {
            float xv = GX(j);
            w += xv - GX(j - 20);            // w ends at j
            float ma = w * 0.05f;
            A  = fmaf(xv, xv, A);
            Bs = fmaf(xv, ma, Bs);
            Cs = fmaf(ma, ma, Cs);
        }
        // w ends t0-1; wd ends t0-21; A,Bs,Cs cover j = t0-20..t0-1
        #pragma unroll 1
        for (int g = 0; g < CH / 4; ++g) {
            float b0[4], b1[4], b2[4], b3[4];
            #pragma unroll
            for (int jj = 0; jj < 4; ++jj) {
                int k = g * 4 + jj;
                int t = t0 + k;
                float xt = so[k];
                float xo = GX(t - 20);
                w  += xt - xo;  float ma  = w  * 0.05f;
                wd += xo - GX(t - 40); float mad = wd * 0.05f;
                A  += xt * xt - xo * xo;
                Bs += xt * ma - xo * mad;
                Cs += ma * ma - mad * mad;
                float var = fmaxf(A - 2.f * Bs + Cs, 0.f) * 0.05f;
                float sd  = sqrtf(var + FEPS);
                float bbu = ma + 2.f * sd;
                float bbl = ma - 2.f * sd;
                b0[jj] = bbu; b1[jj] = ma; b2[jj] = bbl;
                b3[jj] = __fdividef(xt - bbl, bbu - bbl + FEPS);
            }
            int go = g * 4;
            *(float4*)(obase + 12 * BT + go) = make_float4(b0[0], b0[1], b0[2], b0[3]);
            *(float4*)(obase + 13 * BT + go) = make_float4(b1[0], b1[1], b1[2], b1[3]);
            *(float4*)(obase + 14 * BT + go) = make_float4(b2[0], b2[1], b2[2], b2[3]);
            *(float4*)(obase + 15 * BT + go) = make_float4(b3[0], b3[1], b3[2], b3[3]);
        }
    }
}

extern "C" void kernel_launch(void* const* d_in, const int* in_sizes, int n_in,
                              void* d_out, int out_size)
{
    const float* close = (const float*)d_in[0];
    float* out = (float*)d_out;
    int B = in_sizes[0] / TT;                 // 512
    size_t BT = (size_t)B * TT;
    feat_kernel<<<B, NTH>>>(close, out, BT);
}

// round 3
// speedup vs baseline: 2.9367x; 2.8886x over previous
#include <cuda_runtime.h>

#define TT    8192
#define SEG   2048
#define HALO  256
#define TOT   (SEG + HALO)     // 2304
#define NTH   256
#define CH    8                // SEG/NTH
#define CHS   9                // TOT/NTH
#define NW    (NTH/32)
#define FEPS  1e-8f
#define SC_SZ (TOT + TOT/32)   // 2376

__device__ __forceinline__ int PADI(int i){ return i + (i >> 5); }

// inclusive warp scan of affine states: (c,d) means y_out = c*y_in + d
__device__ __forceinline__ void wscan(float& c, float& d, int lane){
    #pragma unroll
    for (int off = 1; off < 32; off <<= 1) {
        float pc = __shfl_up_sync(0xffffffffu, c, off);
        float pd = __shfl_up_sync(0xffffffffu, d, off);
        if (lane >= off) { d = fmaf(pd, c, d); c *= pc; }
    }
}

extern "C" __global__ void __launch_bounds__(NTH, 4)
feat_kernel(const float* __restrict__ gclose, float* __restrict__ gout, size_t BT)
{
    __shared__ float sc[SC_SZ];
    __shared__ float swp[3 * NW];
    __shared__ float si[3 * NTH];

    const int blk  = blockIdx.x;
    const int row  = blk >> 2;
    const int seg  = blk & 3;
    const int tid  = threadIdx.x;
    const int lane = tid & 31;
    const int wid  = tid >> 5;
    const float* x = gclose + (size_t)row * TT;
    const int basem = seg * SEG;          // global t of first emitted element

    // ---- load [basem-HALO, basem+SEG) into skewed smem; left pad with x[0] ----
    {
        const float x0 = x[0];
        #pragma unroll
        for (int j = 0; j < 3; ++j) {
            int i4 = tid + j * NTH;
            if (i4 < TOT / 4) {
                int gi = basem - HALO + i4 * 4;
                float4 v;
                if (gi >= 0) v = *(const float4*)(x + gi);
                else         v = make_float4(x0, x0, x0, x0);
                int b = i4 * 4;
                sc[PADI(b)]     = v.x;
                sc[PADI(b + 1)] = v.y;
                sc[PADI(b + 2)] = v.z;
                sc[PADI(b + 3)] = v.w;
            }
        }
    }
    __syncthreads();

    const float aF = 2.0f / 13.0f, omF = 1.0f - aF;
    const float aS = 2.0f / 27.0f, omS = 1.0f - aS;
    const float aG = 0.2f,         omG = 0.8f;

    // ===== pass A: EMA12/26 affine scan over TOT (CHS=9 per thread) =====
    float yF0, yS0;
    {
        const int s0 = tid * CHS;
        float cF = 1.f, dF = 0.f, cS = 1.f, dS = 0.f;
        #pragma unroll
        for (int k = 0; k < CHS; ++k) {
            float v = sc[PADI(s0 + k)];
            dF = fmaf(aF, v, omF * dF); cF *= omF;
            dS = fmaf(aS, v, omS * dS); cS *= omS;
        }
        wscan(cF, dF, lane);
        wscan(cS, dS, lane);
        if (lane == 31) { swp[wid] = dF; swp[NW + wid] = dS; }
        float uF  = __shfl_up_sync(0xffffffffu, dF, 1);
        float ucF = __shfl_up_sync(0xffffffffu, cF, 1);
        float uS  = __shfl_up_sync(0xffffffffu, dS, 1);
        float ucS = __shfl_up_sync(0xffffffffu, cS, 1);
        __syncthreads();
        // per-warp decay om^288 < 3e-10 -> previous warp's aggregate suffices
        float pF = (wid > 0) ? swp[wid - 1]      : 0.f;
        float pS = (wid > 0) ? swp[NW + wid - 1] : 0.f;
        yF0 = (lane == 0) ? pF : fmaf(ucF, pF, uF);
        yS0 = (lane == 0) ? pS : fmaf(ucS, pS, uS);
    }

    // ===== pass B: EMA9 over macd (replayed) =====
    float y90;
    {
        const int s0 = tid * CHS;
        float yF = yF0, yS = yS0, cG = 1.f, dG = 0.f;
        #pragma unroll
        for (int k = 0; k < CHS; ++k) {
            float v = sc[PADI(s0 + k)];
            yF = fmaf(aF, v, omF * yF);
            yS = fmaf(aS, v, omS * yS);
            float m = yF - yS;
            dG = fmaf(aG, m, omG * dG); cG *= omG;
        }
        wscan(cG, dG, lane);
        if (lane == 31) swp[2 * NW + wid] = dG;
        float uG  = __shfl_up_sync(0xffffffffu, dG, 1);
        float ucG = __shfl_up_sync(0xffffffffu, cG, 1);
        __syncthreads();
        float pG = (wid > 0) ? swp[2 * NW + wid - 1] : 0.f;
        y90 = (lane == 0) ? pG : fmaf(ucG, pG, uG);
    }
    si[tid] = yF0; si[NTH + tid] = yS0; si[2 * NTH + tid] = y90;
    __syncthreads();

    const int i0 = HALO + CH * tid;                 // smem index of first emitted elem
    float* ob = gout + (size_t)row * TT + basem + CH * tid;

    // ===== emit macd(9), signal(10), hist(11) =====
    {
        int c = i0 / CHS;
        int r = i0 - c * CHS;
        float yF = si[c], yS = si[NTH + c], y9 = si[2 * NTH + c];
        int p = c * CHS;
        #pragma unroll 1
        for (int k = 0; k < 9; ++k) {               // r <= 8 replay
            if (k >= r) break;
            float v = sc[PADI(p + k)];
            yF = fmaf(aF, v, omF * yF);
            yS = fmaf(aS, v, omS * yS);
            float m = yF - yS;
            y9 = fmaf(aG, m, omG * y9);
        }
        float* om9 = ob + 9  * BT;
        float* osg = ob + 10 * BT;
        float* oh  = ob + 11 * BT;
        #pragma unroll
        for (int g = 0; g < CH / 4; ++g) {
            float mb[4], sb[4], hb[4];
            #pragma unroll
            for (int jj = 0; jj < 4; ++jj) {
                float v = sc[PADI(i0 + g * 4 + jj)];
                yF = fmaf(aF, v, omF * yF);
                yS = fmaf(aS, v, omS * yS);
                float m = yF - yS;
                y9 = fmaf(aG, m, omG * y9);
                mb[jj] = m; sb[jj] = y9; hb[jj] = m - y9;
            }
            *(float4*)(om9 + g * 4) = make_float4(mb[0], mb[1], mb[2], mb[3]);
            *(float4*)(osg + g * 4) = make_float4(sb[0], sb[1], sb[2], sb[3]);
            *(float4*)(oh  + g * 4) = make_float4(hb[0], hb[1], hb[2], hb[3]);
        }
    }

    // ===== windows: MA5/10/20/50 + ratios (0..7), RSI (8), ATR (16) =====
    {
        float s5 = 0.f, s10 = 0.f, s20 = 0.f, s50 = 0.f, gs = 0.f, ls = 0.f;
        #pragma unroll 1
        for (int k = 1; k <= 50; ++k) {
            float v = sc[PADI(i0 - k)];
            s50 += v;
            if (k <= 20) s20 += v;
            if (k <= 10) s10 += v;
            if (k <= 5)  s5  += v;
        }
        #pragma unroll 1
        for (int k = 1; k <= 14; ++k) {
            float d = sc[PADI(i0 - k)] - sc[PADI(i0 - k - 1)];
            gs += fmaxf(d, 0.f);
            ls += fmaxf(-d, 0.f);
        }
        float xprev = sc[PADI(i0 - 1)];
        float xm15  = sc[PADI(i0 - 15)];
        #pragma unroll
        for (int g = 0; g < CH / 4; ++g) {
            float a0[4], a1[4], a2[4], a3[4], a4[4], a5v[4], a6[4], a7[4], a8[4], a9[4];
            #pragma unroll
            for (int jj = 0; jj < 4; ++jj) {
                int ii = i0 + g * 4 + jj;
                float xt = sc[PADI(ii)];
                s5  += xt - sc[PADI(ii - 5)];
                s10 += xt - sc[PADI(ii - 10)];
                s20 += xt - sc[PADI(ii - 20)];
                s50 += xt - sc[PADI(ii - 50)];
                float d = xt - xprev;
                gs += fmaxf(d, 0.f);
                ls += fmaxf(-d, 0.f);
                float xm14 = sc[PADI(ii - 14)];
                float dl = xm14 - xm15;
                gs -= fmaxf(dl, 0.f);
                ls -= fmaxf(-dl, 0.f);
                xm15 = xm14; xprev = xt;
                float ma5  = s5  * 0.2f;
                float ma10 = s10 * 0.1f;
                float ma20 = s20 * 0.05f;
                float ma50 = s50 * 0.02f;
                a0[jj] = ma5;  a1[jj]  = __fdividef(xt, ma5  + FEPS);
                a2[jj] = ma10; a3[jj]  = __fdividef(xt, ma10 + FEPS);
                a4[jj] = ma20; a5v[jj] = __fdividef(xt, ma20 + FEPS);
                a6[jj] = ma50; a7[jj]  = __fdividef(xt, ma50 + FEPS);
                a8[jj] = 100.f * __fdividef(gs, gs + ls + 14.f * FEPS);
                a9[jj] = (gs + ls) * (1.f / 14.f);
            }
            int go = g * 4;
            *(float4*)(ob + 0  * BT + go) = make_float4(a0[0], a0[1], a0[2], a0[3]);
            *(float4*)(ob + 1  * BT + go) = make_float4(a1[0], a1[1], a1[2], a1[3]);
            *(float4*)(ob + 2  * BT + go) = make_float4(a2[0], a2[1], a2[2], a2[3]);
            *(float4*)(ob + 3  * BT + go) = make_float4(a3[0], a3[1], a3[2], a3[3]);
            *(float4*)(ob + 4  * BT + go) = make_float4(a4[0], a4[1], a4[2], a4[3]);
            *(float4*)(ob + 5  * BT + go) = make_float4(a5v[0], a5v[1], a5v[2], a5v[3]);
            *(float4*)(ob + 6  * BT + go) = make_float4(a6[0], a6[1], a6[2], a6[3]);
            *(float4*)(ob + 7  * BT + go) = make_float4(a7[0], a7[1], a7[2], a7[3]);
            *(float4*)(ob + 8  * BT + go) = make_float4(a8[0], a8[1], a8[2], a8[3]);
            *(float4*)(ob + 16 * BT + go) = make_float4(a9[0], a9[1], a9[2], a9[3]);
        }
    }

    // ===== Bollinger (12,13,14) + %B (15) =====
    {
        float w = 0.f;
        #pragma unroll 1
        for (int k = 21; k <= 40; ++k) w += sc[PADI(i0 - k)];   // 20-sum ending i0-21
        float wd = w;
        float A = 0.f, Bs = 0.f, Cs = 0.f;
        #pragma unroll 1
        for (int j = i0 - 20; j <= i0 - 1; ++j) {
            float xv = sc[PADI(j)];
            w += xv - sc[PADI(j - 20)];
            float ma = w * 0.05f;
            A  = fmaf(xv, xv, A);
            Bs = fmaf(xv, ma, Bs);
            Cs = fmaf(ma, ma, Cs);
        }
        #pragma unroll
        for (int g = 0; g < CH / 4; ++g) {
            float b0[4], b1[4], b2[4], b3[4];
            #pragma unroll
            for (int jj = 0; jj < 4; ++jj) {
                int ii = i0 + g * 4 + jj;
                float xt = sc[PADI(ii)];
                float xo = sc[PADI(ii - 20)];
                w  += xt - xo;             float ma  = w  * 0.05f;
                wd += xo - sc[PADI(ii - 40)]; float mad = wd * 0.05f;
                A  += xt * xt - xo * xo;
                Bs += xt * ma - xo * mad;
                Cs += ma * ma - mad * mad;
                float var = fmaxf(A - 2.f * Bs + Cs, 0.f) * 0.05f;
                float sd  = sqrtf(var + FEPS);
                float bbu = ma + 2.f * sd;
                float bbl = ma - 2.f * sd;
                b0[jj] = bbu; b1[jj] = ma; b2[jj] = bbl;
                b3[jj] = __fdividef(xt - bbl, bbu - bbl + FEPS);
            }
            int go = g * 4;
            *(float4*)(ob + 12 * BT + go) = make_float4(b0[0], b0[1], b0[2], b0[3]);
            *(float4*)(ob + 13 * BT + go) = make_float4(b1[0], b1[1], b1[2], b1[3]);
            *(float4*)(ob + 14 * BT + go) = make_float4(b2[0], b2[1], b2[2], b2[3]);
            *(float4*)(ob + 15 * BT + go) = make_float4(b3[0], b3[1], b3[2], b3[3]);
        }
    }
}

extern "C" void kernel_launch(void* const* d_in, const int* in_sizes, int n_in,
                              void* d_out, int out_size)
{
    const float* close = (const float*)d_in[0];
    float* out = (float*)d_out;
    int B = in_sizes[0] / TT;                 // 512
    size_t BT = (size_t)B * TT;
    feat_kernel<<<B * 4, NTH>>>(close, out, BT);
}